// round 4
// baseline (speedup 1.0000x reference)
#include <cuda_runtime.h>
#include <math.h>

// poses: (4096, 3, 128, 17) float32, channel 1 used.
// out:   [ma(7,4096); mi(7,4096)] — stored as float32 (harness compares in the
//        declared __output__ dtype; integer bins are exactly representable).

#define NB 4096
#define FRAMES 128
#define JOINTS 17
#define ROW_F (FRAMES * JOINTS)   // 2176 floats per (batch, channel)

__global__ __launch_bounds__(128) void divid_part_kernel(
    const float* __restrict__ poses, float* __restrict__ out)
{
    const int b = blockIdx.x;
    const int t = threadIdx.x;   // frame index 0..127

    __shared__ float s[ROW_F];
    __shared__ float red[4][14];

    // Scalar coalesced copy of the channel-1 slice: 2176 floats = 17 * 128 threads.
    const float* g = poses + ((size_t)b * 3 + 1) * ROW_F;
    #pragma unroll
    for (int i = 0; i < JOINTS; i++) {
        const int idx = t + i * FRAMES;
        s[idx] = g[idx];
    }
    __syncthreads();

    // Per-frame alignment; stride 17 (odd) -> bank-conflict-free.
    const float* row = s + t * JOINTS;
    const float x0 = row[0];
    const float ratio = __fmul_rn(__fadd_rn(__fsub_rn(row[5], x0), __fsub_rn(row[6], x0)), 0.5f);

    float v[JOINTS];
    float fm = INFINITY;
    #pragma unroll
    for (int j = 0; j < JOINTS; j++) {
        v[j] = __fdiv_rn(__fsub_rn(row[j], x0), ratio);
        fm = fminf(fm, v[j]);
    }

    // r[0..6] = per-part max, r[7..13] = per-part min (after per-frame min subtraction)
    float r[14];
    #pragma unroll
    for (int k = 0; k < 7; k++) { r[k] = -INFINITY; r[k + 7] = INFINITY; }
    #pragma unroll
    for (int j = 0; j < JOINTS; j++) {
        const int p = (j < 5) ? 0 : ((j - 3) >> 1);   // HEAD/SHOULDER/ELBOW/WRIST/HIP/KNEE/ANKLE
        const float vv = __fsub_rn(v[j], fm);
        r[p]     = fmaxf(r[p], vv);
        r[p + 7] = fminf(r[p + 7], vv);
    }

    // Warp-level reduce 14 values across 32 lanes
    #pragma unroll
    for (int off = 16; off > 0; off >>= 1) {
        #pragma unroll
        for (int k = 0; k < 14; k++) {
            float o = __shfl_down_sync(0xffffffffu, r[k], off);
            r[k] = (k < 7) ? fmaxf(r[k], o) : fminf(r[k], o);
        }
    }

    const int warp = t >> 5, lane = t & 31;
    if (lane == 0) {
        #pragma unroll
        for (int k = 0; k < 14; k++) red[warp][k] = r[k];
    }
    __syncthreads();

    if (t == 0) {
        #pragma unroll
        for (int k = 0; k < 14; k++) {
            float a = red[0][k], c = red[1][k], d = red[2][k], e = red[3][k];
            r[k] = (k < 7) ? fmaxf(fmaxf(a, c), fmaxf(d, e))
                           : fminf(fminf(a, c), fminf(d, e));
        }
        float bottom = r[0], top = r[7];
        #pragma unroll
        for (int p = 1; p < 7; p++) {
            bottom = fmaxf(bottom, r[p]);
            top    = fminf(top,    r[p + 7]);
        }
        const float denom = __fsub_rn(bottom, top);

        #pragma unroll
        for (int p = 0; p < 7; p++) {
            int ma = (int)ceilf (__fmul_rn(__fdiv_rn(__fsub_rn(r[p],     top), denom), 64.0f));
            int mi = (int)floorf(__fmul_rn(__fdiv_rn(__fsub_rn(r[p + 7], top), denom), 64.0f));
            const int hi = (p + 1) * 9, lo = p * 9;
            if (ma <= mi)          { ma = hi; mi = lo; }
            else if (ma - mi > 30) { ma = hi; mi = lo; }
            out[p * NB + b]       = (float)ma;   // store as float32
            out[(7 + p) * NB + b] = (float)mi;
        }
    }
}

extern "C" void kernel_launch(void* const* d_in, const int* in_sizes, int n_in,
                              void* d_out, int out_size)
{
    const float* poses = (const float*)d_in[0];
    float* out = (float*)d_out;
    divid_part_kernel<<<NB, 128>>>(poses, out);
}

// round 7
// speedup vs baseline: 1.0860x; 1.0860x over previous
#include <cuda_runtime.h>
#include <cstdint>
#include <math.h>

// poses: (4096, 3, 128, 17) float32, channel 1 used.
// out:   [ma(7,4096); mi(7,4096)] stored as float32.

#define NB 4096
#define FRAMES 128
#define JOINTS 17
#define ROW_F (FRAMES * JOINTS)   // 2176 floats per (batch, channel); 8704 B (16B-aligned offset)
#define WPB 4                     // warps per block = batches per block

// Monotone bijection float <-> signed int (order-preserving for non-NaN).
__device__ __forceinline__ int f2o(float f) {
    int b = __float_as_int(f);
    return b ^ ((b >> 31) & 0x7fffffff);
}
__device__ __forceinline__ float o2f(int k) {
    return __int_as_float(k ^ ((k >> 31) & 0x7fffffff));
}
__device__ __forceinline__ float warp_max_f32(float v) {
    return o2f(__reduce_max_sync(0xffffffffu, f2o(v)));
}
__device__ __forceinline__ float warp_min_f32(float v) {
    return o2f(__reduce_min_sync(0xffffffffu, f2o(v)));
}

__global__ __launch_bounds__(32 * WPB) void divid_part_kernel(
    const float* __restrict__ poses, float* __restrict__ out)
{
    __shared__ __align__(16) float s[WPB][ROW_F];

    const int lane = threadIdx.x & 31;
    const int w    = threadIdx.x >> 5;
    const int b    = blockIdx.x * WPB + w;

    // ---- Stage channel-1 slice into this warp's smem via cp.async (16B chunks).
    // 2176 floats = 544 float4 = 17 per lane. Global offset (3b+1)*8704 B is 16B-aligned.
    const float4* g4 = reinterpret_cast<const float4*>(poses + ((size_t)b * 3 + 1) * ROW_F);
    unsigned int sbase;
    asm("{ .reg .u64 t; cvta.to.shared.u64 t, %1; cvt.u32.u64 %0, t; }"
        : "=r"(sbase) : "l"(&s[w][0]));
    #pragma unroll
    for (int i = 0; i < 17; i++) {
        const int idx = lane + i * 32;
        asm volatile("cp.async.cg.shared.global [%0], [%1], 16;"
                     :: "r"(sbase + idx * 16), "l"(g4 + idx));
    }
    asm volatile("cp.async.commit_group;");
    asm volatile("cp.async.wait_group 0;");
    __syncwarp();

    // ---- Per-lane: 4 frames (lane, lane+32, lane+64, lane+96); stride-17 rows are
    // bank-conflict-free across lanes (17 odd).
    float r[14];
    #pragma unroll
    for (int k = 0; k < 7; k++) { r[k] = -INFINITY; r[k + 7] = INFINITY; }

    #pragma unroll
    for (int i = 0; i < 4; i++) {
        const float* row = &s[w][(lane + 32 * i) * JOINTS];
        float x[JOINTS];
        #pragma unroll
        for (int j = 0; j < JOINTS; j++) x[j] = row[j];

        const float x0 = x[0];
        const float ratio = __fmul_rn(__fadd_rn(__fsub_rn(x[5], x0), __fsub_rn(x[6], x0)), 0.5f);

        float pmax[7], pmin[7];
        #pragma unroll
        for (int p = 0; p < 7; p++) { pmax[p] = -INFINITY; pmin[p] = INFINITY; }
        #pragma unroll
        for (int j = 0; j < JOINTS; j++) {
            const float v = __fdiv_rn(__fsub_rn(x[j], x0), ratio);
            const int p = (j < 5) ? 0 : ((j - 3) >> 1);
            pmax[p] = fmaxf(pmax[p], v);
            pmin[p] = fminf(pmin[p], v);
        }
        float fm = pmin[0];
        #pragma unroll
        for (int p = 1; p < 7; p++) fm = fminf(fm, pmin[p]);
        // max/min commute with the monotone RN-subtraction of fm -> bit-exact vs reference
        #pragma unroll
        for (int p = 0; p < 7; p++) {
            r[p]     = fmaxf(r[p],     __fsub_rn(pmax[p], fm));
            r[p + 7] = fminf(r[p + 7], __fsub_rn(pmin[p], fm));
        }
    }

    // ---- Warp reduction: 14 integer REDUX ops (result broadcast to all lanes).
    #pragma unroll
    for (int k = 0; k < 7; k++) {
        r[k]     = warp_max_f32(r[k]);
        r[k + 7] = warp_min_f32(r[k + 7]);
    }

    float bottom = r[0], top = r[7];
    #pragma unroll
    for (int p = 1; p < 7; p++) {
        bottom = fmaxf(bottom, r[p]);
        top    = fminf(top,    r[p + 7]);
    }
    const float denom = __fsub_rn(bottom, top);

    // ---- Epilogue: all lanes compute (static indexing), lane 0 stores.
    int ma_[7], mi_[7];
    #pragma unroll
    for (int p = 0; p < 7; p++) {
        int ma = (int)ceilf (__fmul_rn(__fdiv_rn(__fsub_rn(r[p],     top), denom), 64.0f));
        int mi = (int)floorf(__fmul_rn(__fdiv_rn(__fsub_rn(r[p + 7], top), denom), 64.0f));
        const int hi = (p + 1) * 9, lo = p * 9;
        if (ma <= mi || ma - mi > 30) { ma = hi; mi = lo; }
        ma_[p] = ma; mi_[p] = mi;
    }
    if (lane == 0) {
        #pragma unroll
        for (int p = 0; p < 7; p++) {
            out[p * NB + b]       = (float)ma_[p];
            out[(7 + p) * NB + b] = (float)mi_[p];
        }
    }
}

extern "C" void kernel_launch(void* const* d_in, const int* in_sizes, int n_in,
                              void* d_out, int out_size)
{
    const float* poses = (const float*)d_in[0];
    float* out = (float*)d_out;
    divid_part_kernel<<<NB / WPB, 32 * WPB>>>(poses, out);
}

// round 8
// speedup vs baseline: 1.6939x; 1.5598x over previous
#include <cuda_runtime.h>
#include <cstdint>
#include <math.h>

// poses: (4096, 3, 128, 17) float32, channel 1 used.
// out:   [ma(7,4096); mi(7,4096)] stored as float32.

#define NB 4096
#define FRAMES 128
#define JOINTS 17
#define ROW_F (FRAMES * JOINTS)   // 2176 floats per (batch, channel); 8704 B slice, 16B-aligned
#define WPB 4                     // warps per block = batches per block

// Monotone bijection float <-> signed int (order-preserving for non-NaN).
__device__ __forceinline__ int f2o(float f) {
    int b = __float_as_int(f);
    return b ^ ((b >> 31) & 0x7fffffff);
}
__device__ __forceinline__ float o2f(int k) {
    return __int_as_float(k ^ ((k >> 31) & 0x7fffffff));
}
__device__ __forceinline__ float warp_max_f32(float v) {
    return o2f(__reduce_max_sync(0xffffffffu, f2o(v)));
}
__device__ __forceinline__ float warp_min_f32(float v) {
    return o2f(__reduce_min_sync(0xffffffffu, f2o(v)));
}

__global__ __launch_bounds__(32 * WPB) void divid_part_kernel(
    const float* __restrict__ poses, float* __restrict__ out)
{
    __shared__ __align__(16) float s[WPB][ROW_F];

    const int lane = threadIdx.x & 31;
    const int w    = threadIdx.x >> 5;
    const int b    = blockIdx.x * WPB + w;

    // ---- Stage channel-1 slice into this warp's smem via cp.async (16B chunks).
    const float4* g4 = reinterpret_cast<const float4*>(poses + ((size_t)b * 3 + 1) * ROW_F);
    unsigned int sbase;
    asm("{ .reg .u64 t; cvta.to.shared.u64 t, %1; cvt.u32.u64 %0, t; }"
        : "=r"(sbase) : "l"(&s[w][0]));
    #pragma unroll
    for (int i = 0; i < 17; i++) {
        const int idx = lane + i * 32;
        asm volatile("cp.async.cg.shared.global [%0], [%1], 16;"
                     :: "r"(sbase + idx * 16), "l"(g4 + idx));
    }
    asm volatile("cp.async.commit_group;");
    asm volatile("cp.async.wait_group 0;");
    __syncwarp();

    // ---- Per-lane: 4 frames; stride-17 rows are bank-conflict-free (17 odd).
    float r[14];
    #pragma unroll
    for (int k = 0; k < 7; k++) { r[k] = -INFINITY; r[k + 7] = INFINITY; }

    #pragma unroll
    for (int i = 0; i < 4; i++) {
        const float* row = &s[w][(lane + 32 * i) * JOINTS];
        float x[JOINTS];
        #pragma unroll
        for (int j = 0; j < JOINTS; j++) x[j] = row[j];

        const float x0 = x[0];
        const float ratio = __fmul_rn(__fadd_rn(__fsub_rn(x[5], x0), __fsub_rn(x[6], x0)), 0.5f);
        const float rcp = __frcp_rn(ratio);   // one reciprocal; 17 FMULs replace 17 divides

        float v[JOINTS];
        v[0] = 0.0f;                           // (x0 - x0)/ratio == 0 exactly
        #pragma unroll
        for (int j = 1; j < JOINTS; j++)
            v[j] = __fmul_rn(__fsub_rn(x[j], x0), rcp);

        float pmax[7], pmin[7];
        #pragma unroll
        for (int p = 0; p < 7; p++) { pmax[p] = -INFINITY; pmin[p] = INFINITY; }
        #pragma unroll
        for (int j = 0; j < JOINTS; j++) {
            const int p = (j < 5) ? 0 : ((j - 3) >> 1);
            pmax[p] = fmaxf(pmax[p], v[j]);
            pmin[p] = fminf(pmin[p], v[j]);
        }
        float fm = pmin[0];
        #pragma unroll
        for (int p = 1; p < 7; p++) fm = fminf(fm, pmin[p]);
        #pragma unroll
        for (int p = 0; p < 7; p++) {
            r[p]     = fmaxf(r[p],     __fsub_rn(pmax[p], fm));
            r[p + 7] = fminf(r[p + 7], __fsub_rn(pmin[p], fm));
        }
    }

    // ---- Warp reduction: 14 integer REDUX ops (result broadcast to all lanes).
    #pragma unroll
    for (int k = 0; k < 7; k++) {
        r[k]     = warp_max_f32(r[k]);
        r[k + 7] = warp_min_f32(r[k + 7]);
    }

    float bottom = r[0], top = r[7];
    #pragma unroll
    for (int p = 1; p < 7; p++) {
        bottom = fmaxf(bottom, r[p]);
        top    = fminf(top,    r[p + 7]);
    }
    const float denom = __fsub_rn(bottom, top);

    // ---- Epilogue (exact IEEE divides, only 14): all lanes compute, lane 0 stores.
    int ma_[7], mi_[7];
    #pragma unroll
    for (int p = 0; p < 7; p++) {
        int ma = (int)ceilf (__fmul_rn(__fdiv_rn(__fsub_rn(r[p],     top), denom), 64.0f));
        int mi = (int)floorf(__fmul_rn(__fdiv_rn(__fsub_rn(r[p + 7], top), denom), 64.0f));
        const int hi = (p + 1) * 9, lo = p * 9;
        if (ma <= mi || ma - mi > 30) { ma = hi; mi = lo; }
        ma_[p] = ma; mi_[p] = mi;
    }
    if (lane == 0) {
        #pragma unroll
        for (int p = 0; p < 7; p++) {
            out[p * NB + b]       = (float)ma_[p];
            out[(7 + p) * NB + b] = (float)mi_[p];
        }
    }
}

extern "C" void kernel_launch(void* const* d_in, const int* in_sizes, int n_in,
                              void* d_out, int out_size)
{
    const float* poses = (const float*)d_in[0];
    float* out = (float*)d_out;
    divid_part_kernel<<<NB / WPB, 32 * WPB>>>(poses, out);
}